// round 14
// baseline (speedup 1.0000x reference)
#include <cuda_runtime.h>
#include <cuda_fp16.h>
#include <math.h>
#include <stdint.h>

#define D_MODEL 2048
#define B_ROWS  8192
#define KNOW    100
#define NTOK    2
#define NOUT    (NTOK * D_MODEL)     // 4096
#define SCALE_A   64.0f
#define INV_SCALE (1.0f/64.0f)
#define INV32     (1.0f/32.0f)

// ---------------- scratch (static __device__ arrays; no allocation) --------
__device__ __half g_Ehi [(size_t)128 * D_MODEL];
__device__ __half g_Elo [(size_t)128 * D_MODEL];
__device__ __half g_Evhi[(size_t)128 * D_MODEL];
__device__ __half g_Evlo[(size_t)128 * D_MODEL];
__device__ __half g_Phi [(size_t)128 * D_MODEL];
__device__ __half g_Plo [(size_t)128 * D_MODEL];
__device__ float  g_Ppart[(size_t)16 * 128 * D_MODEL];
__device__ float  g_part [(size_t)8 * 128 * NOUT];
__device__ float  g_keys [(size_t)128 * D_MODEL];
__device__ float  g_M    [(size_t)128 * NOUT];
__device__ float  g_spart[(size_t)2 * B_ROWS * 128];
__device__ float  g_c    [128];
__device__ float  g_w    [B_ROWS * 4];
__device__ int    g_idx  [B_ROWS * 4];

// ---------------------------------------------------------------------------
// PTX helpers
// ---------------------------------------------------------------------------
__device__ __forceinline__ uint32_t smem_u32(const void* p) {
    uint32_t a;
    asm("{ .reg .u64 t; cvta.to.shared.u64 t, %1; cvt.u32.u64 %0, t; }"
        : "=r"(a) : "l"(p));
    return a;
}
__device__ __forceinline__ void cp16(uint32_t s, const void* g) {
    asm volatile("cp.async.cg.shared.global [%0], [%1], 16;\n"
                 :: "r"(s), "l"(g) : "memory");
}
__device__ __forceinline__ void cp_commit() {
    asm volatile("cp.async.commit_group;" ::: "memory");
}
__device__ __forceinline__ void cp_wait0() {
    asm volatile("cp.async.wait_group 0;" ::: "memory");
}
__device__ __forceinline__ void cp_wait1() {
    asm volatile("cp.async.wait_group 1;" ::: "memory");
}
__device__ __forceinline__ void ldsm4(uint32_t* d, uint32_t addr) {
    asm volatile("ldmatrix.sync.aligned.m8n8.x4.shared.b16 {%0,%1,%2,%3}, [%4];"
                 : "=r"(d[0]), "=r"(d[1]), "=r"(d[2]), "=r"(d[3]) : "r"(addr));
}
__device__ __forceinline__ void mma16816(float* c, const uint32_t* a, const uint32_t* b) {
    asm volatile(
        "mma.sync.aligned.m16n8k16.row.col.f32.f16.f16.f32 "
        "{%0,%1,%2,%3}, {%4,%5,%6,%7}, {%8,%9}, {%0,%1,%2,%3};"
        : "+f"(c[0]), "+f"(c[1]), "+f"(c[2]), "+f"(c[3])
        : "r"(a[0]), "r"(a[1]), "r"(a[2]), "r"(a[3]), "r"(b[0]), "r"(b[1]));
}
__device__ __forceinline__ void split2h(float x, __half& h, __half& l) {
    h = __float2half_rn(x);
    l = __float2half_rn(x - __half2float(h));
}
__device__ __forceinline__ uint32_t h2u(__half a, __half b) {
    __half2 h = __halves2half2(a, b);
    return *(uint32_t*)&h;
}
__device__ __forceinline__ uint32_t swz(uint32_t o) { return o ^ ((o >> 3) & 0x70); }

#define FUSE_SMEM 99328u

// ---------------------------------------------------------------------------
// BODY: scores tile (64x128), 3-term X split, K-split 2 (16 chunks).
// X staged via REGISTERS (LDG), converted to double-buffered AH/AL smem.
// smem: AH0 0 | AL0 8K | AH1 16K | AL1 24K | B0 32K(hi|lo 16K) | B1 64K = 96K
// (R13-proven)
// ---------------------------------------------------------------------------
__device__ __forceinline__ void body_scores(
    char* smem, const float* __restrict__ X,
    const __half* __restrict__ Phi, const __half* __restrict__ Plo,
    float* __restrict__ spart, int row0, int kidx)
{
    const uint32_t sm = smem_u32(smem);
    const int tid  = threadIdx.x;
    const int warp = tid >> 5, lane = tid & 31;
    const int kbase = kidx * 1024;
    float* outp = spart + (size_t)kidx * B_ROWS * 128;

    const uint32_t B0 = 32768u;

    const __half* b_p[8]; uint32_t b_sm[8];
#pragma unroll
    for (int j = 0; j < 8; j++) {
        int id = tid + 256 * j;
        int part = id >> 10, rem = id & 1023;
        int r = rem >> 3, u = rem & 7;
        b_sm[j] = (uint32_t)part * 16384u + swz((uint32_t)r * 128u + (uint32_t)u * 16u);
        b_p[j]  = (part ? Plo : Phi) + (size_t)r * D_MODEL + kbase + u * 8;
    }

    float acc[2][4][4];
#pragma unroll
    for (int mt = 0; mt < 2; mt++)
#pragma unroll
        for (int nt = 0; nt < 4; nt++)
#pragma unroll
            for (int q = 0; q < 4; q++) acc[mt][nt][q] = 0.f;

#define B_LOAD(ci_)                                                            \
    do {                                                                       \
        int c_k = (ci_);                                                       \
        uint32_t bst = sm + B0 + (uint32_t)(c_k & 1) * 32768u;                 \
        _Pragma("unroll")                                                      \
        for (int j = 0; j < 8; j++) cp16(bst + b_sm[j], b_p[j] + c_k * 64);    \
    } while (0)

    const int m0 = (warp >> 2) * 32, n0 = (warp & 3) * 32;
    const int cr = tid >> 2, cq = tid & 3;
    const float* xrow = X + (size_t)(row0 + cr) * D_MODEL + kbase + cq * 16;

    B_LOAD(0); cp_commit();
    B_LOAD(1); cp_commit();
    float4 xr[4];
#pragma unroll
    for (int k = 0; k < 4; k++) xr[k] = *(const float4*)&xrow[k * 4];

    for (int ci = 0; ci < 16; ci++) {
        const uint32_t As = sm + (uint32_t)(ci & 1) * 16384u;   // AH | AL(+8K)
        {
            float e[16];
#pragma unroll
            for (int k = 0; k < 4; k++) ((float4*)e)[k] = xr[k];
#pragma unroll
            for (int g = 0; g < 2; g++) {
                __half hh[8], ll[8];
#pragma unroll
                for (int m = 0; m < 8; m++) split2h(e[g * 8 + m], hh[m], ll[m]);
                uint32_t so = swz((uint32_t)cr * 128u + (uint32_t)(cq * 2 + g) * 16u);
                uint4 hv, lv;
                hv.x = h2u(hh[0], hh[1]); hv.y = h2u(hh[2], hh[3]);
                hv.z = h2u(hh[4], hh[5]); hv.w = h2u(hh[6], hh[7]);
                lv.x = h2u(ll[0], ll[1]); lv.y = h2u(ll[2], ll[3]);
                lv.z = h2u(ll[4], ll[5]); lv.w = h2u(ll[6], ll[7]);
                *(uint4*)((char*)smem + (As - sm) + so)         = hv;
                *(uint4*)((char*)smem + (As - sm) + 8192u + so) = lv;
            }
        }
        if (ci + 1 < 16) {
#pragma unroll
            for (int k = 0; k < 4; k++)
                xr[k] = *(const float4*)&xrow[(ci + 1) * 64 + k * 4];
        }
        cp_wait1();
        __syncthreads();

        const uint32_t Bso = sm + B0 + (uint32_t)(ci & 1) * 32768u;
#pragma unroll
        for (int ks = 0; ks < 4; ks++) {
            uint32_t ah[2][4], al[2][4];
#pragma unroll
            for (int mt = 0; mt < 2; mt++) {
                int r = m0 + mt * 16 + (lane & 15);
                int u = ks * 2 + (lane >> 4);
                uint32_t off = (uint32_t)r * 128u + (uint32_t)((u ^ (r & 7)) * 16);
                ldsm4(ah[mt], As + off);
                ldsm4(al[mt], As + 8192u + off);
            }
            uint32_t bh[4][2], bl[4][2];
#pragma unroll
            for (int bt = 0; bt < 2; bt++) {
                int r = n0 + bt * 16 + (lane & 15);
                int u = ks * 2 + (lane >> 4);
                uint32_t off = (uint32_t)r * 128u + (uint32_t)((u ^ (r & 7)) * 16);
                uint32_t t[4];
                ldsm4(t, Bso + off);
                bh[2 * bt][0] = t[0]; bh[2 * bt][1] = t[2];
                bh[2 * bt + 1][0] = t[1]; bh[2 * bt + 1][1] = t[3];
                ldsm4(t, Bso + 16384u + off);
                bl[2 * bt][0] = t[0]; bl[2 * bt][1] = t[2];
                bl[2 * bt + 1][0] = t[1]; bl[2 * bt + 1][1] = t[3];
            }
#pragma unroll
            for (int mt = 0; mt < 2; mt++)
#pragma unroll
                for (int nt = 0; nt < 4; nt++) {
                    mma16816(acc[mt][nt], ah[mt], bh[nt]);
                    mma16816(acc[mt][nt], ah[mt], bl[nt]);
                    mma16816(acc[mt][nt], al[mt], bh[nt]);
                }
        }
        __syncthreads();
        if (ci + 2 < 16) B_LOAD(ci + 2);
        cp_commit();
    }
#undef B_LOAD

#pragma unroll
    for (int mt = 0; mt < 2; mt++) {
#pragma unroll
        for (int nt = 0; nt < 4; nt++) {
            int r = row0 + m0 + mt * 16 + (lane >> 2);
            int c = n0 + nt * 8 + (lane & 3) * 2;
            float2 s0, s1;
            s0.x = acc[mt][nt][0]; s0.y = acc[mt][nt][1];
            s1.x = acc[mt][nt][2]; s1.y = acc[mt][nt][3];
            *(float2*)&outp[(size_t)r * 128 + c]       = s0;
            *(float2*)&outp[(size_t)(r + 8) * 128 + c] = s1;
        }
    }
}

// ---------------------------------------------------------------------------
// BODY: 2-term HMMA NT GEMM, kslice=256 (two 128-k blocks, persistent acc),
// B fp32 direct-to-regs quantization. (R11 convert + R12 kb2 loop, both proven)
// smem: A 64K (AHc0|AHc1|ALc0|ALc1 @16K each) | BH0 16K | BH1 16K = 96K
// ---------------------------------------------------------------------------
#define BH2OFF 65536u

__device__ __forceinline__ void body_h2t32(
    char* smem, const __half* __restrict__ Ahi, const __half* __restrict__ Alo,
    const float* __restrict__ Bw, float* __restrict__ C, int N,
    int col0, int kbase)
{
    const uint32_t sm = smem_u32(smem);
    const int tid  = threadIdx.x;
    const int warp = tid >> 5, lane = tid & 31;

    float acc[2][8][4];
#pragma unroll
    for (int mt = 0; mt < 2; mt++)
#pragma unroll
        for (int nt = 0; nt < 8; nt++)
#pragma unroll
            for (int q = 0; q < 4; q++) acc[mt][nt][q] = 0.f;

    const int m0 = (warp >> 1) * 32, n0 = (warp & 1) * 64;

    for (int kb2 = 0; kb2 < 2; kb2++) {
        const int kb = kbase + kb2 * 128;
        // A loads: 64KB via cp.async
#pragma unroll
        for (int j = 0; j < 16; j++) {
            int id = tid + 256 * j;
            int sel = id >> 10;                // 0:AHc0 1:AHc1 2:ALc0 3:ALc1
            int rem = id & 1023;
            int r = rem >> 3, u = rem & 7;
            int ci = sel & 1;
            const __half* src = (sel >> 1) ? Alo : Ahi;
            uint32_t dst = sm + (uint32_t)(sel >> 1) * 32768u + (uint32_t)ci * 16384u +
                           swz((uint32_t)r * 128u + (uint32_t)u * 16u);
            cp16(dst, src + (size_t)r * D_MODEL + kb + ci * 64 + u * 8);
        }
        cp_commit();

        for (int ci = 0; ci < 2; ci++) {
            float4 breg[8];
#pragma unroll
            for (int j = 0; j < 8; j++) {
                int id = tid + 256 * j;
                int r = id >> 4, u = id & 15;
                breg[j] = *(const float4*)&Bw[(size_t)(col0 + r) * D_MODEL +
                                              kb + ci * 64 + u * 4];
            }
            if (ci == 0) cp_wait0();
#pragma unroll
            for (int j = 0; j < 8; j++) {
                int id = tid + 256 * j;
                int r = id >> 4, u = id & 15;
                uint2 v;
                v.x = h2u(__float2half_rn(breg[j].x), __float2half_rn(breg[j].y));
                v.y = h2u(__float2half_rn(breg[j].z), __float2half_rn(breg[j].w));
                *(uint2*)(smem + BH2OFF + ci * 16384 +
                          swz((uint32_t)r * 128u + (uint32_t)u * 8u)) = v;
            }
            __syncthreads();

            const uint32_t AHb = sm + (uint32_t)ci * 16384u;
            const uint32_t ALb = AHb + 32768u;
            const uint32_t Bso = sm + BH2OFF + (uint32_t)ci * 16384u;
#pragma unroll
            for (int ks = 0; ks < 4; ks++) {
                uint32_t ah[2][4], al[2][4];
#pragma unroll
                for (int mt = 0; mt < 2; mt++) {
                    int r = m0 + mt * 16 + (lane & 15);
                    int u = ks * 2 + (lane >> 4);
                    uint32_t off = (uint32_t)r * 128u + (uint32_t)((u ^ (r & 7)) * 16);
                    ldsm4(ah[mt], AHb + off);
                    ldsm4(al[mt], ALb + off);
                }
                uint32_t bf[8][2];
#pragma unroll
                for (int bt = 0; bt < 4; bt++) {
                    uint32_t t[4];
                    int r = n0 + bt * 16 + (lane & 15);
                    int u = ks * 2 + (lane >> 4);
                    ldsm4(t, Bso + (uint32_t)r * 128u + (uint32_t)((u ^ (r & 7)) * 16));
                    bf[2 * bt][0] = t[0]; bf[2 * bt][1] = t[2];
                    bf[2 * bt + 1][0] = t[1]; bf[2 * bt + 1][1] = t[3];
                }
#pragma unroll
                for (int mt = 0; mt < 2; mt++)
#pragma unroll
                    for (int nt = 0; nt < 8; nt++) {
                        mma16816(acc[mt][nt], ah[mt], bf[nt]);
                        mma16816(acc[mt][nt], al[mt], bf[nt]);
                    }
            }
        }
        __syncthreads();   // A/BH reuse barrier before next k-block
    }

#pragma unroll
    for (int mt = 0; mt < 2; mt++) {
#pragma unroll
        for (int nt = 0; nt < 8; nt++) {
            int r = m0 + mt * 16 + (lane >> 2);
            int c = col0 + n0 + nt * 8 + (lane & 3) * 2;
            float2 v0, v1;
            v0.x = acc[mt][nt][0] * INV_SCALE; v0.y = acc[mt][nt][1] * INV_SCALE;
            v1.x = acc[mt][nt][2] * INV_SCALE; v1.y = acc[mt][nt][3] * INV_SCALE;
            *(float2*)&C[(size_t)r * N + c]       = v0;
            *(float2*)&C[(size_t)(r + 8) * N + c] = v1;
        }
    }
}

// ---------------------------------------------------------------------------
// BODY: fp32 SIMT NN GEMM (P partials), dynamic smem. (proven)
// ---------------------------------------------------------------------------
__device__ __forceinline__ void body_gemm_nn_P(
    char* smemraw, const float* __restrict__ A, const float* __restrict__ B,
    float* __restrict__ C, int col0, int kbase)
{
    float (*As)[132] = reinterpret_cast<float(*)[132]>(smemraw);
    float (*Bs)[128] = reinterpret_cast<float(*)[128]>(smemraw + 8448);
    const int tid = threadIdx.x;
    const int tm = tid >> 4, tn = tid & 15;
    float acc[8][8];
#pragma unroll
    for (int i = 0; i < 8; i++)
#pragma unroll
        for (int j = 0; j < 8; j++) acc[i][j] = 0.f;

    for (int k0 = kbase; k0 < kbase + 128; k0 += 16) {
#pragma unroll
        for (int j = 0; j < 2; j++) {
            int i = tid + 256 * j;
            int r = i >> 2, kq = i & 3;
            float4 v = *(const float4*)&A[(size_t)r * D_MODEL + k0 + kq * 4];
            As[kq * 4 + 0][r] = v.x; As[kq * 4 + 1][r] = v.y;
            As[kq * 4 + 2][r] = v.z; As[kq * 4 + 3][r] = v.w;
        }
#pragma unroll
        for (int j = 0; j < 2; j++) {
            int i = tid + 256 * j;
            int r = i >> 5, c4 = i & 31;
            float4 v = *(const float4*)&B[(size_t)(k0 + r) * D_MODEL + col0 + c4 * 4];
            *(float4*)&Bs[r][c4 * 4] = v;
        }
        __syncthreads();
#pragma unroll
        for (int k = 0; k < 16; k++) {
            float a[8], b[8];
            *(float4*)&a[0] = *(const float4*)&As[k][tm * 8 + 0];
            *(float4*)&a[4] = *(const float4*)&As[k][tm * 8 + 4];
            *(float4*)&b[0] = *(const float4*)&Bs[k][tn * 8 + 0];
            *(float4*)&b[4] = *(const float4*)&Bs[k][tn * 8 + 4];
#pragma unroll
            for (int i = 0; i < 8; i++)
#pragma unroll
                for (int j = 0; j < 8; j++) acc[i][j] += a[i] * b[j];
        }
        __syncthreads();
    }
#pragma unroll
    for (int i = 0; i < 8; i++) {
        int r = tm * 8 + i;
#pragma unroll
        for (int j = 0; j < 8; j += 4) {
            float4 v; v.x = acc[i][j]; v.y = acc[i][j + 1];
            v.z = acc[i][j + 2]; v.w = acc[i][j + 3];
            *(float4*)&C[(size_t)r * D_MODEL + col0 + tn * 8 + j] = v;
        }
    }
}

// ---------------------------------------------------------------------------
// FUSED KERNEL 1: prep = pad_keys+c (blocks 0..127) | split_pad_emb (128..383)
// ---------------------------------------------------------------------------
__global__ __launch_bounds__(256)
void prep_fused(const float* __restrict__ keysin, const float* __restrict__ bq,
                const float* __restrict__ emb,
                float* __restrict__ keysout, float* __restrict__ c,
                __half* __restrict__ Ehi, __half* __restrict__ Elo)
{
    const int tid = threadIdx.x;
    if (blockIdx.x < 128) {
        __shared__ float red[8];
        const int row = blockIdx.x;
        const int lane = tid & 31, wid = tid >> 5;
        float part = 0.f;
#pragma unroll
        for (int j = 0; j < 2; j++) {
            int i = tid + 256 * j;
            float4 v; v.x = v.y = v.z = v.w = 0.f;
            if (row < KNOW) v = ((const float4*)keysin)[row * 512 + i];
            ((float4*)keysout)[row * 512 + i] = v;
            float4 b = ((const float4*)bq)[i];
            part += v.x * b.x + v.y * b.y + v.z * b.z + v.w * b.w;
        }
#pragma unroll
        for (int o = 16; o > 0; o >>= 1) part += __shfl_xor_sync(0xffffffffu, part, o);
        if (lane == 0) red[wid] = part;
        __syncthreads();
        if (tid == 0) {
            float s = 0.f;
#pragma unroll
            for (int k = 0; k < 8; k++) s += red[k];
            c[row] = (row < KNOW) ? s : -1e30f;
        }
    } else {
        int gid = (blockIdx.x - 128) * 256 + tid;
        int row = gid >> 9;
        float4 v;
        if (row < KNOW) v = ((const float4*)emb)[gid];
        else { v.x = v.y = v.z = v.w = 0.f; }
        v.x *= SCALE_A; v.y *= SCALE_A; v.z *= SCALE_A; v.w *= SCALE_A;
        __half h0, h1, h2, h3, l0, l1, l2, l3;
        split2h(v.x, h0, l0); split2h(v.y, h1, l1);
        split2h(v.z, h2, l2); split2h(v.w, h3, l3);
        *(__half2*)&Ehi[(size_t)gid * 4]     = __halves2half2(h0, h1);
        *(__half2*)&Ehi[(size_t)gid * 4 + 2] = __halves2half2(h2, h3);
        *(__half2*)&Elo[(size_t)gid * 4]     = __halves2half2(l0, l1);
        *(__half2*)&Elo[(size_t)gid * 4 + 2] = __halves2half2(l2, l3);
    }
}

// ---------------------------------------------------------------------------
// FUSED KERNEL 2: gemm_nn_P (0..255) | gemm_h2t32 Ev ksplit8 (256..383)
// ---------------------------------------------------------------------------
__global__ __launch_bounds__(256, 2)
void dual_gemm1(const float* __restrict__ keys, const float* __restrict__ Wq,
                float* __restrict__ Pp,
                const __half* __restrict__ Ehi, const __half* __restrict__ Elo,
                const float* __restrict__ Wv, float* __restrict__ part)
{
    extern __shared__ char smem[];
    const int bx = blockIdx.x;
    if (bx < 256) {
        body_gemm_nn_P(smem, keys, Wq,
                       Pp + (size_t)(bx >> 4) * 128 * D_MODEL,
                       (bx & 15) * 128, (bx >> 4) * 128);
    } else {
        int id = bx - 256;          // 0..127: col = id&15 (16), ks = id>>4 (8)
        body_h2t32(smem, Ehi, Elo, Wv,
                   part + (size_t)(id >> 4) * 128 * D_MODEL, D_MODEL,
                   (id & 15) * 128, (id >> 4) * 256);
    }
}

// ---------------------------------------------------------------------------
// FUSED KERNEL 3: reduceP_split 16-part (0..255) | reduceEv_split 8-part (256..511)
// ---------------------------------------------------------------------------
__global__ __launch_bounds__(256)
void reduce_fused(const float* __restrict__ Pp,
                  __half* __restrict__ Phi, __half* __restrict__ Plo,
                  const float* __restrict__ part, const float* __restrict__ bv,
                  __half* __restrict__ Evhi, __half* __restrict__ Evlo)
{
    const int tid = threadIdx.x;
    if (blockIdx.x < 256) {
        int gid = blockIdx.x * 256 + tid;
        const float4* p = (const float4*)Pp;
        float4 r; r.x = r.y = r.z = r.w = 0.f;
#pragma unroll
        for (int s = 0; s < 16; s++) {
            float4 a = p[gid + (size_t)s * 65536];
            r.x += a.x; r.y += a.y; r.z += a.z; r.w += a.w;
        }
        r.x *= 32.f; r.y *= 32.f; r.z *= 32.f; r.w *= 32.f;
        __half h0, h1, h2, h3, l0, l1, l2, l3;
        split2h(r.x, h0, l0); split2h(r.y, h1, l1);
        split2h(r.z, h2, l2); split2h(r.w, h3, l3);
        *(__half2*)&Phi[(size_t)gid * 4]     = __halves2half2(h0, h1);
        *(__half2*)&Phi[(size_t)gid * 4 + 2] = __halves2half2(h2, h3);
        *(__half2*)&Plo[(size_t)gid * 4]     = __halves2half2(l0, l1);
        *(__half2*)&Plo[(size_t)gid * 4 + 2] = __halves2half2(l2, l3);
    } else {
        int gid = (blockIdx.x - 256) * 256 + tid;
        const float4* pp = (const float4*)part;
        float4 r; r.x = r.y = r.z = r.w = 0.f;
#pragma unroll
        for (int s = 0; s < 8; s++) {
            float4 a = pp[gid + (size_t)s * 65536];
            r.x += a.x; r.y += a.y; r.z += a.z; r.w += a.w;
        }
        float4 b = ((const float4*)bv)[gid & 511];
        r.x = (r.x + b.x) * SCALE_A; r.y = (r.y + b.y) * SCALE_A;
        r.z = (r.z + b.z) * SCALE_A; r.w = (r.w + b.w) * SCALE_A;
        __half h0, h1, h2, h3, l0, l1, l2, l3;
        split2h(r.x, h0, l0); split2h(r.y, h1, l1);
        split2h(r.z, h2, l2); split2h(r.w, h3, l3);
        *(__half2*)&Evhi[(size_t)gid * 4]     = __halves2half2(h0, h1);
        *(__half2*)&Evhi[(size_t)gid * 4 + 2] = __halves2half2(h2, h3);
        *(__half2*)&Evlo[(size_t)gid * 4]     = __halves2half2(l0, l1);
        *(__half2*)&Evlo[(size_t)gid * 4 + 2] = __halves2half2(l2, l3);
    }
}

// ---------------------------------------------------------------------------
// FUSED KERNEL 4: scores (0..255, K-split 2) | gemm_h2t32 M ksplit8 (256..511)
// ---------------------------------------------------------------------------
__global__ __launch_bounds__(256, 2)
void dual2(const float* __restrict__ X,
           const __half* __restrict__ Phi, const __half* __restrict__ Plo,
           float* __restrict__ spart,
           const __half* __restrict__ Evhi, const __half* __restrict__ Evlo,
           const float* __restrict__ Wo, float* __restrict__ part)
{
    extern __shared__ char smem[];
    const int bx = blockIdx.x;
    if (bx < 256) {
        body_scores(smem, X, Phi, Plo, spart, (bx & 127) * 64, bx >> 7);
    } else {
        int id = bx - 256;          // 0..255: col = id&31 (32), ks = id>>5 (8)
        body_h2t32(smem, Evhi, Evlo, Wo,
                   part + (size_t)(id >> 5) * 128 * NOUT, NOUT,
                   (id & 31) * 128, (id >> 5) * 256);
    }
}

// ---------------------------------------------------------------------------
// FUSED KERNEL 5: topk (0..1023) | reduceM 8-part +bo (1024..1535)
// ---------------------------------------------------------------------------
__global__ __launch_bounds__(256)
void topk_reduceM(const float* __restrict__ spart, const float* __restrict__ cbias,
                  float* __restrict__ wout, int* __restrict__ iout,
                  const float* __restrict__ part, const float* __restrict__ bo,
                  float* __restrict__ M)
{
    const int tid = threadIdx.x;
    if (blockIdx.x < 1024) {
        __shared__ float sc[8][128];
        const int warp = tid >> 5;
        const int lane = tid & 31;
        const int row  = blockIdx.x * 8 + warp;
        const float scale = rsqrtf((float)D_MODEL);
#pragma unroll
        for (int t = 0; t < 4; t++) {
            int key = lane + 32 * t;
            float s = spart[(size_t)row * 128 + key] +
                      spart[(size_t)(B_ROWS + row) * 128 + key];
            sc[warp][key] = (s * INV32 + cbias[key]) * scale;
        }
        __syncwarp();
        if (lane == 0) {
            float s0 = -INFINITY, s1 = -INFINITY, s2 = -INFINITY;
            int   i0 = 0, i1 = 0, i2 = 0;
            for (int i = 0; i < KNOW; i++) {
                float s = sc[warp][i];
                if (s > s0)      { s2 = s1; i2 = i1; s1 = s0; i1 = i0; s0 = s; i0 = i; }
                else if (s > s1) { s2 = s1; i2 = i1; s1 = s;  i1 = i; }
                else if (s > s2) { s2 = s;  i2 = i; }
            }
            float e1 = expf(s1 - s0);
            float e2 = expf(s2 - s0);
            float inv = 1.f / (1.f + e1 + e2);
            wout[row * 4 + 0] = inv;
            wout[row * 4 + 1] = e1 * inv;
            wout[row * 4 + 2] = e2 * inv;
            iout[row * 4 + 0] = i0;
            iout[row * 4 + 1] = i1;
            iout[row * 4 + 2] = i2;
        }
    } else {
        int gid = (blockIdx.x - 1024) * 256 + tid;
        const float4* pp = (const float4*)part;
        float4 r; r.x = r.y = r.z = r.w = 0.f;
#pragma unroll
        for (int s = 0; s < 8; s++) {
            float4 a = pp[gid + (size_t)s * 131072];
            r.x += a.x; r.y += a.y; r.z += a.z; r.w += a.w;
        }
        float4 b = ((const float4*)bo)[gid & 1023];
        r.x += b.x; r.y += b.y; r.z += b.z; r.w += b.w;
        ((float4*)M)[gid] = r;
    }
}

// ---------------------------------------------------------------------------
// out[t][b][cc] = sum_k w_bk * M'[idx_bk][t*2048+cc]
// ---------------------------------------------------------------------------
__global__ __launch_bounds__(256)
void out_gather(const float* __restrict__ M,
                const float* __restrict__ w, const int* __restrict__ idx,
                float* __restrict__ out)
{
    int gid = blockIdx.x * 256 + threadIdx.x;
    int row = gid >> 10;
    int c4  = gid & 1023;

    float w0 = w[row * 4 + 0], w1 = w[row * 4 + 1], w2 = w[row * 4 + 2];
    int   i0 = idx[row * 4 + 0], i1 = idx[row * 4 + 1], i2 = idx[row * 4 + 2];

    const float4* M4 = (const float4*)M;
    float4 a = M4[(size_t)i0 * 1024 + c4];
    float4 b = M4[(size_t)i1 * 1024 + c4];
    float4 c = M4[(size_t)i2 * 1024 + c4];

    float4 r;
    r.x = w0 * a.x + w1 * b.x + w2 * c.x;
    r.y = w0 * a.y + w1 * b.y + w2 * c.y;
    r.z = w0 * a.z + w1 * b.z + w2 * c.z;
    r.w = w0 * a.w + w1 * b.w + w2 * c.w;

    int col = c4 * 4;
    int t = col >> 11, cc = col & 2047;
    *(float4*)&out[((size_t)t * B_ROWS + row) * D_MODEL + cc] = r;
}

// ---------------------------------------------------------------------------
extern "C" void kernel_launch(void* const* d_in, const int* in_sizes, int n_in,
                              void* d_out, int out_size)
{
    const float* query  = (const float*)d_in[0];
    const float* Wq     = (const float*)d_in[1];
    const float* bq     = (const float*)d_in[2];
    const float* Wv     = (const float*)d_in[3];
    const float* bv     = (const float*)d_in[4];
    const float* Wo     = (const float*)d_in[5];
    const float* bo     = (const float*)d_in[6];
    const float* K_emb  = (const float*)d_in[7];
    const float* K_keys = (const float*)d_in[8];
    float* out = (float*)d_out;

    __half *Ehi, *Elo, *Evhi, *Evlo, *Phi, *Plo;
    float *Pp, *part, *keys, *M, *sp, *c, *w;
    int *idx;
    cudaGetSymbolAddress((void**)&Ehi,  g_Ehi);
    cudaGetSymbolAddress((void**)&Elo,  g_Elo);
    cudaGetSymbolAddress((void**)&Evhi, g_Evhi);
    cudaGetSymbolAddress((void**)&Evlo, g_Evlo);
    cudaGetSymbolAddress((void**)&Phi,  g_Phi);
    cudaGetSymbolAddress((void**)&Plo,  g_Plo);
    cudaGetSymbolAddress((void**)&Pp,   g_Ppart);
    cudaGetSymbolAddress((void**)&part, g_part);
    cudaGetSymbolAddress((void**)&keys, g_keys);
    cudaGetSymbolAddress((void**)&M,    g_M);
    cudaGetSymbolAddress((void**)&sp,   g_spart);
    cudaGetSymbolAddress((void**)&c,    g_c);
    cudaGetSymbolAddress((void**)&w,    g_w);
    cudaGetSymbolAddress((void**)&idx,  g_idx);

    cudaFuncSetAttribute(dual_gemm1, cudaFuncAttributeMaxDynamicSharedMemorySize, FUSE_SMEM);
    cudaFuncSetAttribute(dual2,      cudaFuncAttributeMaxDynamicSharedMemorySize, FUSE_SMEM);

    // 1) prep: pad keys + c  |  split/pad K_emb
    prep_fused<<<384, 256>>>(K_keys, bq, K_emb, keys, c, Ehi, Elo);

    // 2) P = keys @ Wq (K-split 16)  |  Ev partials (K-split 8)
    dual_gemm1<<<384, 256, FUSE_SMEM>>>(keys, Wq, Pp, Ehi, Elo, Wv, part);

    // 3) reduce P -> Phi/Plo  |  reduce Ev (+bv) -> Evhi/Evlo
    reduce_fused<<<512, 256>>>(Pp, Phi, Plo, part, bv, Evhi, Evlo);

    // 4) scores partials (K-split 2)  |  M partials (K-split 8)
    dual2<<<512, 256, FUSE_SMEM>>>(query, Phi, Plo, sp, Evhi, Evlo, Wo, part);

    // 5) top-3 + softmax  |  reduce M (+bo) -> M'
    topk_reduceM<<<1536, 256>>>(sp, c, w, idx, part, bo, M);

    // 6) final gather
    out_gather<<<(B_ROWS * (NOUT / 4)) / 256, 256>>>(M, w, idx, out);
}

// round 15
// speedup vs baseline: 1.0655x; 1.0655x over previous
#include <cuda_runtime.h>
#include <cuda_fp16.h>
#include <math.h>
#include <stdint.h>

#define D_MODEL 2048
#define B_ROWS  8192
#define KNOW    100
#define NTOK    2
#define NOUT    (NTOK * D_MODEL)     // 4096
#define SCALE_A   64.0f
#define INV_SCALE (1.0f/64.0f)
#define INV32     (1.0f/32.0f)

// ---------------- scratch (static __device__ arrays; no allocation) --------
__device__ __half g_Ehi [(size_t)128 * D_MODEL];
__device__ __half g_Elo [(size_t)128 * D_MODEL];
__device__ __half g_Evhi[(size_t)128 * D_MODEL];
__device__ __half g_Evlo[(size_t)128 * D_MODEL];
__device__ __half g_Phi [(size_t)128 * D_MODEL];
__device__ __half g_Plo [(size_t)128 * D_MODEL];
__device__ float  g_Ppart[(size_t)16 * 128 * D_MODEL];
__device__ float  g_part [(size_t)16 * 128 * NOUT];
__device__ float  g_keys [(size_t)128 * D_MODEL];
__device__ float  g_M    [(size_t)128 * NOUT];
__device__ float  g_spart[(size_t)2 * B_ROWS * 128];
__device__ float  g_c    [128];
__device__ float  g_w    [B_ROWS * 4];
__device__ int    g_idx  [B_ROWS * 4];

// ---------------------------------------------------------------------------
// PTX helpers
// ---------------------------------------------------------------------------
__device__ __forceinline__ uint32_t smem_u32(const void* p) {
    uint32_t a;
    asm("{ .reg .u64 t; cvta.to.shared.u64 t, %1; cvt.u32.u64 %0, t; }"
        : "=r"(a) : "l"(p));
    return a;
}
__device__ __forceinline__ void cp16(uint32_t s, const void* g) {
    asm volatile("cp.async.cg.shared.global [%0], [%1], 16;\n"
                 :: "r"(s), "l"(g) : "memory");
}
__device__ __forceinline__ void cp_commit() {
    asm volatile("cp.async.commit_group;" ::: "memory");
}
__device__ __forceinline__ void cp_wait0() {
    asm volatile("cp.async.wait_group 0;" ::: "memory");
}
__device__ __forceinline__ void cp_wait1() {
    asm volatile("cp.async.wait_group 1;" ::: "memory");
}
__device__ __forceinline__ void ldsm4(uint32_t* d, uint32_t addr) {
    asm volatile("ldmatrix.sync.aligned.m8n8.x4.shared.b16 {%0,%1,%2,%3}, [%4];"
                 : "=r"(d[0]), "=r"(d[1]), "=r"(d[2]), "=r"(d[3]) : "r"(addr));
}
__device__ __forceinline__ void mma16816(float* c, const uint32_t* a, const uint32_t* b) {
    asm volatile(
        "mma.sync.aligned.m16n8k16.row.col.f32.f16.f16.f32 "
        "{%0,%1,%2,%3}, {%4,%5,%6,%7}, {%8,%9}, {%0,%1,%2,%3};"
        : "+f"(c[0]), "+f"(c[1]), "+f"(c[2]), "+f"(c[3])
        : "r"(a[0]), "r"(a[1]), "r"(a[2]), "r"(a[3]), "r"(b[0]), "r"(b[1]));
}
__device__ __forceinline__ void split2h(float x, __half& h, __half& l) {
    h = __float2half_rn(x);
    l = __float2half_rn(x - __half2float(h));
}
__device__ __forceinline__ uint32_t h2u(__half a, __half b) {
    __half2 h = __halves2half2(a, b);
    return *(uint32_t*)&h;
}
__device__ __forceinline__ uint32_t swz(uint32_t o) { return o ^ ((o >> 3) & 0x70); }

#define FUSE_SMEM 99328u

// ---------------------------------------------------------------------------
// BODY: scores tile (64x128), 3-term X split, K-split 2 (16 chunks).
// X via registers; convert for chunk ci+1 issued AFTER MMA(ci) so the ALU
// convert overlaps the tensor-pipe burst (software pipelined, 1-iter skew).
// smem: AH0 0 | AL0 8K | AH1 16K | AL1 24K | B0 32K(hi|lo 16K) | B1 64K = 96K
// ---------------------------------------------------------------------------
__device__ __forceinline__ void sc_convert(char* smem, uint32_t abase,
                                           const float4* xr, int cr, int cq)
{
    float e[16];
#pragma unroll
    for (int k = 0; k < 4; k++) ((float4*)e)[k] = xr[k];
#pragma unroll
    for (int g = 0; g < 2; g++) {
        __half hh[8], ll[8];
#pragma unroll
        for (int m = 0; m < 8; m++) split2h(e[g * 8 + m], hh[m], ll[m]);
        uint32_t so = swz((uint32_t)cr * 128u + (uint32_t)(cq * 2 + g) * 16u);
        uint4 hv, lv;
        hv.x = h2u(hh[0], hh[1]); hv.y = h2u(hh[2], hh[3]);
        hv.z = h2u(hh[4], hh[5]); hv.w = h2u(hh[6], hh[7]);
        lv.x = h2u(ll[0], ll[1]); lv.y = h2u(ll[2], ll[3]);
        lv.z = h2u(ll[4], ll[5]); lv.w = h2u(ll[6], ll[7]);
        *(uint4*)(smem + abase + so)         = hv;
        *(uint4*)(smem + abase + 8192u + so) = lv;
    }
}

__device__ __forceinline__ void body_scores(
    char* smem, const float* __restrict__ X,
    const __half* __restrict__ Phi, const __half* __restrict__ Plo,
    float* __restrict__ spart, int row0, int kidx)
{
    const uint32_t sm = smem_u32(smem);
    const int tid  = threadIdx.x;
    const int warp = tid >> 5, lane = tid & 31;
    const int kbase = kidx * 1024;
    float* outp = spart + (size_t)kidx * B_ROWS * 128;

    const uint32_t B0 = 32768u;

    const __half* b_p[8]; uint32_t b_sm[8];
#pragma unroll
    for (int j = 0; j < 8; j++) {
        int id = tid + 256 * j;
        int part = id >> 10, rem = id & 1023;
        int r = rem >> 3, u = rem & 7;
        b_sm[j] = (uint32_t)part * 16384u + swz((uint32_t)r * 128u + (uint32_t)u * 16u);
        b_p[j]  = (part ? Plo : Phi) + (size_t)r * D_MODEL + kbase + u * 8;
    }

    float acc[2][4][4];
#pragma unroll
    for (int mt = 0; mt < 2; mt++)
#pragma unroll
        for (int nt = 0; nt < 4; nt++)
#pragma unroll
            for (int q = 0; q < 4; q++) acc[mt][nt][q] = 0.f;

#define B_LOAD(ci_)                                                            \
    do {                                                                       \
        int c_k = (ci_);                                                       \
        uint32_t bst = sm + B0 + (uint32_t)(c_k & 1) * 32768u;                 \
        _Pragma("unroll")                                                      \
        for (int j = 0; j < 8; j++) cp16(bst + b_sm[j], b_p[j] + c_k * 64);    \
    } while (0)

    const int m0 = (warp >> 2) * 32, n0 = (warp & 3) * 32;
    const int cr = tid >> 2, cq = tid & 3;
    const float* xrow = X + (size_t)(row0 + cr) * D_MODEL + kbase + cq * 16;

    // prologue: 2 B chunks in flight; convert(0) -> A0; xr holds chunk 1
    B_LOAD(0); cp_commit();
    B_LOAD(1); cp_commit();
    float4 xr[4];
#pragma unroll
    for (int k = 0; k < 4; k++) xr[k] = *(const float4*)&xrow[k * 4];
    sc_convert(smem, 0u, xr, cr, cq);
#pragma unroll
    for (int k = 0; k < 4; k++) xr[k] = *(const float4*)&xrow[64 + k * 4];

    for (int ci = 0; ci < 16; ci++) {
        const uint32_t As = sm + (uint32_t)(ci & 1) * 16384u;   // AH | AL(+8K)
        cp_wait1();              // B(ci) arrived
        __syncthreads();         // A(ci) stores + B(ci) visible

        // MMA(ci) — convert(ci+1) interleaves below (different pipes)
        const uint32_t Bso = sm + B0 + (uint32_t)(ci & 1) * 32768u;
#pragma unroll
        for (int ks = 0; ks < 4; ks++) {
            uint32_t ah[2][4], al[2][4];
#pragma unroll
            for (int mt = 0; mt < 2; mt++) {
                int r = m0 + mt * 16 + (lane & 15);
                int u = ks * 2 + (lane >> 4);
                uint32_t off = (uint32_t)r * 128u + (uint32_t)((u ^ (r & 7)) * 16);
                ldsm4(ah[mt], As + off);
                ldsm4(al[mt], As + 8192u + off);
            }
            uint32_t bh[4][2], bl[4][2];
#pragma unroll
            for (int bt = 0; bt < 2; bt++) {
                int r = n0 + bt * 16 + (lane & 15);
                int u = ks * 2 + (lane >> 4);
                uint32_t off = (uint32_t)r * 128u + (uint32_t)((u ^ (r & 7)) * 16);
                uint32_t t[4];
                ldsm4(t, Bso + off);
                bh[2 * bt][0] = t[0]; bh[2 * bt][1] = t[2];
                bh[2 * bt + 1][0] = t[1]; bh[2 * bt + 1][1] = t[3];
                ldsm4(t, Bso + 16384u + off);
                bl[2 * bt][0] = t[0]; bl[2 * bt][1] = t[2];
                bl[2 * bt + 1][0] = t[1]; bl[2 * bt + 1][1] = t[3];
            }
#pragma unroll
            for (int mt = 0; mt < 2; mt++)
#pragma unroll
                for (int nt = 0; nt < 4; nt++) {
                    mma16816(acc[mt][nt], ah[mt], bh[nt]);
                    mma16816(acc[mt][nt], ah[mt], bl[nt]);
                    mma16816(acc[mt][nt], al[mt], bh[nt]);
                }
        }

        // convert(ci+1) into the other A buffer (overlaps MMA issue above)
        if (ci + 1 < 16)
            sc_convert(smem, (uint32_t)((ci + 1) & 1) * 16384u, xr, cr, cq);
        // prefetch X chunk ci+2 to regs
        if (ci + 2 < 16) {
#pragma unroll
            for (int k = 0; k < 4; k++)
                xr[k] = *(const float4*)&xrow[(ci + 2) * 64 + k * 4];
        }

        __syncthreads();         // MMA(ci) done before B(ci+2) overwrites
        if (ci + 2 < 16) B_LOAD(ci + 2);
        cp_commit();
    }
#undef B_LOAD

#pragma unroll
    for (int mt = 0; mt < 2; mt++) {
#pragma unroll
        for (int nt = 0; nt < 4; nt++) {
            int r = row0 + m0 + mt * 16 + (lane >> 2);
            int c = n0 + nt * 8 + (lane & 3) * 2;
            float2 s0, s1;
            s0.x = acc[mt][nt][0]; s0.y = acc[mt][nt][1];
            s1.x = acc[mt][nt][2]; s1.y = acc[mt][nt][3];
            *(float2*)&outp[(size_t)r * 128 + c]       = s0;
            *(float2*)&outp[(size_t)(r + 8) * 128 + c] = s1;
        }
    }
}

// ---------------------------------------------------------------------------
// BODY v2: 2-term HMMA NT GEMM, B fp32 direct-to-regs quantization. (R11/R13)
// smem: A 64K (AHc0|AHc1|ALc0|ALc1 @16K each) | BH0 16K | BH1 16K = 96K
// ---------------------------------------------------------------------------
#define BH2OFF 65536u

__device__ __forceinline__ void body_h2t32(
    char* smem, const __half* __restrict__ Ahi, const __half* __restrict__ Alo,
    const float* __restrict__ Bw, float* __restrict__ C, int N,
    int col0, int kbase)
{
    const uint32_t sm = smem_u32(smem);
    const int tid  = threadIdx.x;
    const int warp = tid >> 5, lane = tid & 31;

    // A prologue: all 64KB via cp.async
#pragma unroll
    for (int j = 0; j < 16; j++) {
        int id = tid + 256 * j;
        int sel = id >> 10;                // 0:AHc0 1:AHc1 2:ALc0 3:ALc1
        int rem = id & 1023;
        int r = rem >> 3, u = rem & 7;
        int ci = sel & 1;
        const __half* src = (sel >> 1) ? Alo : Ahi;
        uint32_t dst = sm + (uint32_t)(sel >> 1) * 32768u + (uint32_t)ci * 16384u +
                       swz((uint32_t)r * 128u + (uint32_t)u * 16u);
        cp16(dst, src + (size_t)r * D_MODEL + kbase + ci * 64 + u * 8);
    }
    cp_commit();

    float acc[2][8][4];
#pragma unroll
    for (int mt = 0; mt < 2; mt++)
#pragma unroll
        for (int nt = 0; nt < 8; nt++)
#pragma unroll
            for (int q = 0; q < 4; q++) acc[mt][nt][q] = 0.f;

    const int m0 = (warp >> 1) * 32, n0 = (warp & 1) * 64;

    for (int ci = 0; ci < 2; ci++) {
        float4 breg[8];
#pragma unroll
        for (int j = 0; j < 8; j++) {
            int id = tid + 256 * j;
            int r = id >> 4, u = id & 15;
            breg[j] = *(const float4*)&Bw[(size_t)(col0 + r) * D_MODEL +
                                          kbase + ci * 64 + u * 4];
        }
        if (ci == 0) cp_wait0();
#pragma unroll
        for (int j = 0; j < 8; j++) {
            int id = tid + 256 * j;
            int r = id >> 4, u = id & 15;
            uint2 v;
            v.x = h2u(__float2half_rn(breg[j].x), __float2half_rn(breg[j].y));
            v.y = h2u(__float2half_rn(breg[j].z), __float2half_rn(breg[j].w));
            *(uint2*)(smem + BH2OFF + ci * 16384 +
                      swz((uint32_t)r * 128u + (uint32_t)u * 8u)) = v;
        }
        __syncthreads();

        const uint32_t AHb = sm + (uint32_t)ci * 16384u;
        const uint32_t ALb = AHb + 32768u;
        const uint32_t Bso = sm + BH2OFF + (uint32_t)ci * 16384u;
#pragma unroll
        for (int ks = 0; ks < 4; ks++) {
            uint32_t ah[2][4], al[2][4];
#pragma unroll
            for (int mt = 0; mt < 2; mt++) {
                int r = m0 + mt * 16 + (lane & 15);
                int u = ks * 2 + (lane >> 4);
                uint32_t off = (uint32_t)r * 128u + (uint32_t)((u ^ (r & 7)) * 16);
                ldsm4(ah[mt], AHb + off);
                ldsm4(al[mt], ALb + off);
            }
            uint32_t bf[8][2];
#pragma unroll
            for (int bt = 0; bt < 4; bt++) {
                uint32_t t[4];
                int r = n0 + bt * 16 + (lane & 15);
                int u = ks * 2 + (lane >> 4);
                ldsm4(t, Bso + (uint32_t)r * 128u + (uint32_t)((u ^ (r & 7)) * 16));
                bf[2 * bt][0] = t[0]; bf[2 * bt][1] = t[2];
                bf[2 * bt + 1][0] = t[1]; bf[2 * bt + 1][1] = t[3];
            }
#pragma unroll
            for (int mt = 0; mt < 2; mt++)
#pragma unroll
                for (int nt = 0; nt < 8; nt++) {
                    mma16816(acc[mt][nt], ah[mt], bf[nt]);
                    mma16816(acc[mt][nt], al[mt], bf[nt]);
                }
        }
    }

#pragma unroll
    for (int mt = 0; mt < 2; mt++) {
#pragma unroll
        for (int nt = 0; nt < 8; nt++) {
            int r = m0 + mt * 16 + (lane >> 2);
            int c = col0 + n0 + nt * 8 + (lane & 3) * 2;
            float2 v0, v1;
            v0.x = acc[mt][nt][0] * INV_SCALE; v0.y = acc[mt][nt][1] * INV_SCALE;
            v1.x = acc[mt][nt][2] * INV_SCALE; v1.y = acc[mt][nt][3] * INV_SCALE;
            *(float2*)&C[(size_t)r * N + c]       = v0;
            *(float2*)&C[(size_t)(r + 8) * N + c] = v1;
        }
    }
}

// ---------------------------------------------------------------------------
// BODY: fp32 SIMT NN GEMM (P partials), dynamic smem. (proven)
// ---------------------------------------------------------------------------
__device__ __forceinline__ void body_gemm_nn_P(
    char* smemraw, const float* __restrict__ A, const float* __restrict__ B,
    float* __restrict__ C, int col0, int kbase)
{
    float (*As)[132] = reinterpret_cast<float(*)[132]>(smemraw);
    float (*Bs)[128] = reinterpret_cast<float(*)[128]>(smemraw + 8448);
    const int tid = threadIdx.x;
    const int tm = tid >> 4, tn = tid & 15;
    float acc[8][8];
#pragma unroll
    for (int i = 0; i < 8; i++)
#pragma unroll
        for (int j = 0; j < 8; j++) acc[i][j] = 0.f;

    for (int k0 = kbase; k0 < kbase + 128; k0 += 16) {
#pragma unroll
        for (int j = 0; j < 2; j++) {
            int i = tid + 256 * j;
            int r = i >> 2, kq = i & 3;
            float4 v = *(const float4*)&A[(size_t)r * D_MODEL + k0 + kq * 4];
            As[kq * 4 + 0][r] = v.x; As[kq * 4 + 1][r] = v.y;
            As[kq * 4 + 2][r] = v.z; As[kq * 4 + 3][r] = v.w;
        }
#pragma unroll
        for (int j = 0; j < 2; j++) {
            int i = tid + 256 * j;
            int r = i >> 5, c4 = i & 31;
            float4 v = *(const float4*)&B[(size_t)(k0 + r) * D_MODEL + col0 + c4 * 4];
            *(float4*)&Bs[r][c4 * 4] = v;
        }
        __syncthreads();
#pragma unroll
        for (int k = 0; k < 16; k++) {
            float a[8], b[8];
            *(float4*)&a[0] = *(const float4*)&As[k][tm * 8 + 0];
            *(float4*)&a[4] = *(const float4*)&As[k][tm * 8 + 4];
            *(float4*)&b[0] = *(const float4*)&Bs[k][tn * 8 + 0];
            *(float4*)&b[4] = *(const float4*)&Bs[k][tn * 8 + 4];
#pragma unroll
            for (int i = 0; i < 8; i++)
#pragma unroll
                for (int j = 0; j < 8; j++) acc[i][j] += a[i] * b[j];
        }
        __syncthreads();
    }
#pragma unroll
    for (int i = 0; i < 8; i++) {
        int r = tm * 8 + i;
#pragma unroll
        for (int j = 0; j < 8; j += 4) {
            float4 v; v.x = acc[i][j]; v.y = acc[i][j + 1];
            v.z = acc[i][j + 2]; v.w = acc[i][j + 3];
            *(float4*)&C[(size_t)r * D_MODEL + col0 + tn * 8 + j] = v;
        }
    }
}

// ---------------------------------------------------------------------------
// FUSED KERNEL 1: prep = pad_keys+c (blocks 0..127) | split_pad_emb (128..383)
// ---------------------------------------------------------------------------
__global__ __launch_bounds__(256)
void prep_fused(const float* __restrict__ keysin, const float* __restrict__ bq,
                const float* __restrict__ emb,
                float* __restrict__ keysout, float* __restrict__ c,
                __half* __restrict__ Ehi, __half* __restrict__ Elo)
{
    const int tid = threadIdx.x;
    if (blockIdx.x < 128) {
        __shared__ float red[8];
        const int row = blockIdx.x;
        const int lane = tid & 31, wid = tid >> 5;
        float part = 0.f;
#pragma unroll
        for (int j = 0; j < 2; j++) {
            int i = tid + 256 * j;
            float4 v; v.x = v.y = v.z = v.w = 0.f;
            if (row < KNOW) v = ((const float4*)keysin)[row * 512 + i];
            ((float4*)keysout)[row * 512 + i] = v;
            float4 b = ((const float4*)bq)[i];
            part += v.x * b.x + v.y * b.y + v.z * b.z + v.w * b.w;
        }
#pragma unroll
        for (int o = 16; o > 0; o >>= 1) part += __shfl_xor_sync(0xffffffffu, part, o);
        if (lane == 0) red[wid] = part;
        __syncthreads();
        if (tid == 0) {
            float s = 0.f;
#pragma unroll
            for (int k = 0; k < 8; k++) s += red[k];
            c[row] = (row < KNOW) ? s : -1e30f;
        }
    } else {
        int gid = (blockIdx.x - 128) * 256 + tid;
        int row = gid >> 9;
        float4 v;
        if (row < KNOW) v = ((const float4*)emb)[gid];
        else { v.x = v.y = v.z = v.w = 0.f; }
        v.x *= SCALE_A; v.y *= SCALE_A; v.z *= SCALE_A; v.w *= SCALE_A;
        __half h0, h1, h2, h3, l0, l1, l2, l3;
        split2h(v.x, h0, l0); split2h(v.y, h1, l1);
        split2h(v.z, h2, l2); split2h(v.w, h3, l3);
        *(__half2*)&Ehi[(size_t)gid * 4]     = __halves2half2(h0, h1);
        *(__half2*)&Ehi[(size_t)gid * 4 + 2] = __halves2half2(h2, h3);
        *(__half2*)&Elo[(size_t)gid * 4]     = __halves2half2(l0, l1);
        *(__half2*)&Elo[(size_t)gid * 4 + 2] = __halves2half2(l2, l3);
    }
}

// ---------------------------------------------------------------------------
// FUSED KERNEL 2: gemm_nn_P (0..255) | gemm_h2t32 Ev ksplit16 (256..511)
// ---------------------------------------------------------------------------
__global__ __launch_bounds__(256, 2)
void dual_gemm1(const float* __restrict__ keys, const float* __restrict__ Wq,
                float* __restrict__ Pp,
                const __half* __restrict__ Ehi, const __half* __restrict__ Elo,
                const float* __restrict__ Wv, float* __restrict__ part)
{
    extern __shared__ char smem[];
    const int bx = blockIdx.x;
    if (bx < 256) {
        body_gemm_nn_P(smem, keys, Wq,
                       Pp + (size_t)(bx >> 4) * 128 * D_MODEL,
                       (bx & 15) * 128, (bx >> 4) * 128);
    } else {
        int id = bx - 256;
        body_h2t32(smem, Ehi, Elo, Wv,
                   part + (size_t)(id >> 4) * 128 * D_MODEL, D_MODEL,
                   (id & 15) * 128, (id >> 4) * 128);
    }
}

// ---------------------------------------------------------------------------
// FUSED KERNEL 3: reduceP_split (0..255) | reduceEv_split (256..511)
// ---------------------------------------------------------------------------
__global__ __launch_bounds__(256)
void reduce_fused(const float* __restrict__ Pp,
                  __half* __restrict__ Phi, __half* __restrict__ Plo,
                  const float* __restrict__ part, const float* __restrict__ bv,
                  __half* __restrict__ Evhi, __half* __restrict__ Evlo)
{
    const int tid = threadIdx.x;
    if (blockIdx.x < 256) {
        int gid = blockIdx.x * 256 + tid;
        const float4* p = (const float4*)Pp;
        float4 r; r.x = r.y = r.z = r.w = 0.f;
#pragma unroll
        for (int s = 0; s < 16; s++) {
            float4 a = p[gid + (size_t)s * 65536];
            r.x += a.x; r.y += a.y; r.z += a.z; r.w += a.w;
        }
        r.x *= 32.f; r.y *= 32.f; r.z *= 32.f; r.w *= 32.f;
        __half h0, h1, h2, h3, l0, l1, l2, l3;
        split2h(r.x, h0, l0); split2h(r.y, h1, l1);
        split2h(r.z, h2, l2); split2h(r.w, h3, l3);
        *(__half2*)&Phi[(size_t)gid * 4]     = __halves2half2(h0, h1);
        *(__half2*)&Phi[(size_t)gid * 4 + 2] = __halves2half2(h2, h3);
        *(__half2*)&Plo[(size_t)gid * 4]     = __halves2half2(l0, l1);
        *(__half2*)&Plo[(size_t)gid * 4 + 2] = __halves2half2(l2, l3);
    } else {
        int gid = (blockIdx.x - 256) * 256 + tid;
        const float4* pp = (const float4*)part;
        float4 r; r.x = r.y = r.z = r.w = 0.f;
#pragma unroll
        for (int s = 0; s < 16; s++) {
            float4 a = pp[gid + (size_t)s * 65536];
            r.x += a.x; r.y += a.y; r.z += a.z; r.w += a.w;
        }
        float4 b = ((const float4*)bv)[gid & 511];
        r.x = (r.x + b.x) * SCALE_A; r.y = (r.y + b.y) * SCALE_A;
        r.z = (r.z + b.z) * SCALE_A; r.w = (r.w + b.w) * SCALE_A;
        __half h0, h1, h2, h3, l0, l1, l2, l3;
        split2h(r.x, h0, l0); split2h(r.y, h1, l1);
        split2h(r.z, h2, l2); split2h(r.w, h3, l3);
        *(__half2*)&Evhi[(size_t)gid * 4]     = __halves2half2(h0, h1);
        *(__half2*)&Evhi[(size_t)gid * 4 + 2] = __halves2half2(h2, h3);
        *(__half2*)&Evlo[(size_t)gid * 4]     = __halves2half2(l0, l1);
        *(__half2*)&Evlo[(size_t)gid * 4 + 2] = __halves2half2(l2, l3);
    }
}

// ---------------------------------------------------------------------------
// FUSED KERNEL 4: scores (0..255, K-split 2) | gemm_h2t32 M ksplit16 (256..767)
// ---------------------------------------------------------------------------
__global__ __launch_bounds__(256, 2)
void dual2(const float* __restrict__ X,
           const __half* __restrict__ Phi, const __half* __restrict__ Plo,
           float* __restrict__ spart,
           const __half* __restrict__ Evhi, const __half* __restrict__ Evlo,
           const float* __restrict__ Wo, float* __restrict__ part)
{
    extern __shared__ char smem[];
    const int bx = blockIdx.x;
    if (bx < 256) {
        body_scores(smem, X, Phi, Plo, spart, (bx & 127) * 64, bx >> 7);
    } else {
        int id = bx - 256;          // 0..511: col = id&31 (32), ks = id>>5 (16)
        body_h2t32(smem, Evhi, Evlo, Wo,
                   part + (size_t)(id >> 5) * 128 * NOUT, NOUT,
                   (id & 31) * 128, (id >> 5) * 128);
    }
}

// ---------------------------------------------------------------------------
// FUSED KERNEL 5: topk (0..1023) | reduceM+bo (1024..1535)
// ---------------------------------------------------------------------------
__global__ __launch_bounds__(256)
void topk_reduceM(const float* __restrict__ spart, const float* __restrict__ cbias,
                  float* __restrict__ wout, int* __restrict__ iout,
                  const float* __restrict__ part, const float* __restrict__ bo,
                  float* __restrict__ M)
{
    const int tid = threadIdx.x;
    if (blockIdx.x < 1024) {
        __shared__ float sc[8][128];
        const int warp = tid >> 5;
        const int lane = tid & 31;
        const int row  = blockIdx.x * 8 + warp;
        const float scale = rsqrtf((float)D_MODEL);
#pragma unroll
        for (int t = 0; t < 4; t++) {
            int key = lane + 32 * t;
            float s = spart[(size_t)row * 128 + key] +
                      spart[(size_t)(B_ROWS + row) * 128 + key];
            sc[warp][key] = (s * INV32 + cbias[key]) * scale;
        }
        __syncwarp();
        if (lane == 0) {
            float s0 = -INFINITY, s1 = -INFINITY, s2 = -INFINITY;
            int   i0 = 0, i1 = 0, i2 = 0;
            for (int i = 0; i < KNOW; i++) {
                float s = sc[warp][i];
                if (s > s0)      { s2 = s1; i2 = i1; s1 = s0; i1 = i0; s0 = s; i0 = i; }
                else if (s > s1) { s2 = s1; i2 = i1; s1 = s;  i1 = i; }
                else if (s > s2) { s2 = s;  i2 = i; }
            }
            float e1 = expf(s1 - s0);
            float e2 = expf(s2 - s0);
            float inv = 1.f / (1.f + e1 + e2);
            wout[row * 4 + 0] = inv;
            wout[row * 4 + 1] = e1 * inv;
            wout[row * 4 + 2] = e2 * inv;
            iout[row * 4 + 0] = i0;
            iout[row * 4 + 1] = i1;
            iout[row * 4 + 2] = i2;
        }
    } else {
        int gid = (blockIdx.x - 1024) * 256 + tid;
        const float4* pp = (const float4*)part;
        float4 r; r.x = r.y = r.z = r.w = 0.f;
#pragma unroll
        for (int s = 0; s < 16; s++) {
            float4 a = pp[gid + (size_t)s * 131072];
            r.x += a.x; r.y += a.y; r.z += a.z; r.w += a.w;
        }
        float4 b = ((const float4*)bo)[gid & 1023];
        r.x += b.x; r.y += b.y; r.z += b.z; r.w += b.w;
        ((float4*)M)[gid] = r;
    }
}

// ---------------------------------------------------------------------------
// out[t][b][cc] = sum_k w_bk * M'[idx_bk][t*2048+cc]
// ---------------------------------------------------------------------------
__global__ __launch_bounds__(256)
void out_gather(const float* __restrict__ M,
                const float* __restrict__ w, const int* __restrict__ idx,
                float* __restrict__ out)
{
    int gid = blockIdx.x * 256 + threadIdx.x;
    int row = gid >> 10;
    int c4  = gid & 1023;

    float w0 = w[row * 4 + 0], w1 = w[row * 4 + 1], w2 = w[row * 4 + 2];
    int   i0 = idx[row * 4 + 0], i1 = idx[row * 4 + 1], i2 = idx[row * 4 + 2];

    const float4* M4 = (const float4*)M;
    float4 a = M4[(size_t)i0 * 1024 + c4];
    float4 b = M4[(size_t)i1 * 1024 + c4];
    float4 c = M4[(size_t)i2 * 1024 + c4];

    float4 r;
    r.x = w0 * a.x + w1 * b.x + w2 * c.x;
    r.y = w0 * a.y + w1 * b.y + w2 * c.y;
    r.z = w0 * a.z + w1 * b.z + w2 * c.z;
    r.w = w0 * a.w + w1 * b.w + w2 * c.w;

    int col = c4 * 4;
    int t = col >> 11, cc = col & 2047;
    *(float4*)&out[((size_t)t * B_ROWS + row) * D_MODEL + cc] = r;
}

// ---------------------------------------------------------------------------
extern "C" void kernel_launch(void* const* d_in, const int* in_sizes, int n_in,
                              void* d_out, int out_size)
{
    const float* query  = (const float*)d_in[0];
    const float* Wq     = (const float*)d_in[1];
    const float* bq     = (const float*)d_in[2];
    const float* Wv     = (const float*)d_in[3];
    const float* bv     = (const float*)d_in[4];
    const float* Wo     = (const float*)d_in[5];
    const float* bo     = (const float*)d_in[6];
    const float* K_emb  = (const float*)d_in[7];
    const float* K_keys = (const float*)d_in[8];
    float* out = (float*)d_out;

    __half *Ehi, *Elo, *Evhi, *Evlo, *Phi, *Plo;
    float *Pp, *part, *keys, *M, *sp, *c, *w;
    int *idx;
    cudaGetSymbolAddress((void**)&Ehi,  g_Ehi);
    cudaGetSymbolAddress((void**)&Elo,  g_Elo);
    cudaGetSymbolAddress((void**)&Evhi, g_Evhi);
    cudaGetSymbolAddress((void**)&Evlo, g_Evlo);
    cudaGetSymbolAddress((void**)&Phi,  g_Phi);
    cudaGetSymbolAddress((void**)&Plo,  g_Plo);
    cudaGetSymbolAddress((void**)&Pp,   g_Ppart);
    cudaGetSymbolAddress((void**)&part, g_part);
    cudaGetSymbolAddress((void**)&keys, g_keys);
    cudaGetSymbolAddress((void**)&M,    g_M);
    cudaGetSymbolAddress((void**)&sp,   g_spart);
    cudaGetSymbolAddress((void**)&c,    g_c);
    cudaGetSymbolAddress((void**)&w,    g_w);
    cudaGetSymbolAddress((void**)&idx,  g_idx);

    cudaFuncSetAttribute(dual_gemm1, cudaFuncAttributeMaxDynamicSharedMemorySize, FUSE_SMEM);
    cudaFuncSetAttribute(dual2,      cudaFuncAttributeMaxDynamicSharedMemorySize, FUSE_SMEM);

    // 1) prep: pad keys + c  |  split/pad K_emb
    prep_fused<<<384, 256>>>(K_keys, bq, K_emb, keys, c, Ehi, Elo);

    // 2) P = keys @ Wq (K-split 16)  |  Ev partials (K-split 16)
    dual_gemm1<<<512, 256, FUSE_SMEM>>>(keys, Wq, Pp, Ehi, Elo, Wv, part);

    // 3) reduce P -> Phi/Plo  |  reduce Ev (+bv) -> Evhi/Evlo
    reduce_fused<<<512, 256>>>(Pp, Phi, Plo, part, bv, Evhi, Evlo);

    // 4) scores partials (pipelined convert-after-MMA, K-split 2)  |  M partials (K-split 16)
    dual2<<<768, 256, FUSE_SMEM>>>(query, Phi, Plo, sp, Evhi, Evlo, Wo, part);

    // 5) top-3 + softmax  |  reduce M (+bo) -> M'
    topk_reduceM<<<1536, 256>>>(sp, c, w, idx, part, bo, M);

    // 6) final gather
    out_gather<<<(B_ROWS * (NOUT / 4)) / 256, 256>>>(M, w, idx, out);
}